// round 15
// baseline (speedup 1.0000x reference)
#include <cuda_runtime.h>
#include <cuda_fp16.h>
#include <math.h>
#include <stdint.h>

#define BATCH 256
#define TT    1024
#define NBL   96
#define NT    512
#define TILEB 32768          /* one 128x128-half chunk, bytes */
#define WOFF  65536          /* 2 stages */
#define MBOFF 198656         /* WOFF + max W tile 133120 */
#define DSMEM 198784

// ---------------- static device state ----------------
// h ring, tile-major + swizzled: [slot][batch-half][col-block][128r x 128c halves]
__device__ __align__(1024) __half g_hc3[3][2][8][16384];
__device__ __half g_w1p[2048 * 512];       // permuted Whh1, row p = hid*4+gate
__device__ __half g_w2p[2048 * 1024];      // permuted [Wih2 | Whh2] stacked in K
__device__ float  g_bs1p[2048];
__device__ float  g_bs2p[2048];
__device__ float  g_wih1p[2048];
__device__ float  g_xt[TT * BATCH];
__device__ unsigned g_pc1[2][4];           // L1 publish counters [half][group]
__device__ unsigned g_pc2[2][4];           // L2 publish counters [half][group]
__device__ unsigned g_pcl2[2];             // L2 aggregate (backpressure)

__global__ void init_kernel(const float* __restrict__ x,
                            const float* __restrict__ Wih1,
                            const float* __restrict__ Whh1,
                            const float* __restrict__ bih1, const float* __restrict__ bhh1,
                            const float* __restrict__ Wih2,
                            const float* __restrict__ Whh2,
                            const float* __restrict__ bih2, const float* __restrict__ bhh2) {
    int i = blockIdx.x * blockDim.x + threadIdx.x;
    if (i < 8)  { g_pc1[i >> 2][i & 3] = 0u; g_pc2[i >> 2][i & 3] = 0u; }
    if (i < 2)  g_pcl2[i] = 0u;
    if (i < 2048) {
        int orig = (i & 3) * 512 + (i >> 2);
        g_bs1p[i]  = bih1[orig] + bhh1[orig];
        g_bs2p[i]  = bih2[orig] + bhh2[orig];
        g_wih1p[i] = Wih1[orig];
    }
    if (i < 2048 * 512) {
        int p = i >> 9, c = i & 511;
        int orig = (p & 3) * 512 + (p >> 2);
        g_w1p[i] = __float2half_rn(Whh1[orig * 512 + c]);
    }
    if (i < 2048 * 1024) {
        int p = i >> 10, c = i & 1023;
        int orig = (p & 3) * 512 + (p >> 2);
        float v = (c < 512) ? Wih2[orig * 512 + c] : Whh2[orig * 512 + (c - 512)];
        g_w2p[i] = __float2half_rn(v);
    }
    if (i < 3 * 2 * 8 * 16384) ((__half*)g_hc3)[i] = __float2half_rn(0.f);
    if (i < BATCH * TT) {
        int b = i >> 10, kk = i & 1023;
        g_xt[kk * BATCH + b] = x[i];
    }
}

// ---- MUFU activations ----
__device__ __forceinline__ float ex2f(float v) {
    float r; asm("ex2.approx.ftz.f32 %0, %1;" : "=f"(r) : "f"(v)); return r;
}
__device__ __forceinline__ float rcpf(float v) {
    float r; asm("rcp.approx.ftz.f32 %0, %1;" : "=f"(r) : "f"(v)); return r;
}
__device__ __forceinline__ float sigf(float v) {
    return rcpf(1.f + ex2f(v * -1.4426950408889634f));
}
__device__ __forceinline__ float tanhf_(float v) {
    return fmaf(-2.f, rcpf(ex2f(v * 2.8853900817779268f) + 1.f), 1.f);
}

// ---- PTX helpers ----
__device__ __forceinline__ void cp_cg(uint32_t dst, const void* src) {
    asm volatile("cp.async.cg.shared.global [%0], [%1], 16;" :: "r"(dst), "l"(src));
}
__device__ __forceinline__ void cp_commit() { asm volatile("cp.async.commit_group;"); }
template<int N> __device__ __forceinline__ void cp_wait() {
    asm volatile("cp.async.wait_group %0;" :: "n"(N));
}
__device__ __forceinline__ void ldsm4(uint32_t& r0, uint32_t& r1, uint32_t& r2,
                                      uint32_t& r3, uint32_t addr) {
    asm volatile("ldmatrix.sync.aligned.m8n8.x4.shared.b16 {%0,%1,%2,%3}, [%4];"
                 : "=r"(r0), "=r"(r1), "=r"(r2), "=r"(r3) : "r"(addr));
}
__device__ __forceinline__ void mma16816(float* acc, uint32_t a0, uint32_t a1,
                                         uint32_t a2, uint32_t a3,
                                         uint32_t b0, uint32_t b1) {
    asm volatile(
        "mma.sync.aligned.m16n8k16.row.col.f32.f16.f16.f32 "
        "{%0,%1,%2,%3},{%4,%5,%6,%7},{%8,%9},{%0,%1,%2,%3};"
        : "+f"(acc[0]), "+f"(acc[1]), "+f"(acc[2]), "+f"(acc[3])
        : "r"(a0), "r"(a1), "r"(a2), "r"(a3), "r"(b0), "r"(b1));
}
__device__ __forceinline__ void mbar_init(uint32_t a, uint32_t cnt) {
    asm volatile("mbarrier.init.shared.b64 [%0], %1;" :: "r"(a), "r"(cnt) : "memory");
}
__device__ __forceinline__ void bulk_ld(uint32_t dst, const void* src, uint32_t mb) {
    asm volatile("mbarrier.arrive.expect_tx.shared.b64 _, [%0], %1;"
                 :: "r"(mb), "r"((uint32_t)TILEB) : "memory");
    asm volatile("cp.async.bulk.shared::cluster.global.mbarrier::complete_tx::bytes "
                 "[%0], [%1], %2, [%3];"
                 :: "r"(dst), "l"(src), "r"((uint32_t)TILEB), "r"(mb) : "memory");
}
__device__ __forceinline__ void mbar_wait(uint32_t a, unsigned ph) {
    asm volatile(
        "{\n\t.reg .pred P;\n\t"
        "MW_%=:\n\t"
        "mbarrier.try_wait.parity.acquire.cta.shared::cta.b64 P, [%0], %1;\n\t"
        "@!P bra MW_%=;\n\t}"
        :: "r"(a), "r"(ph) : "memory");
}
__device__ __forceinline__ uint32_t swz(uint32_t b) { return b ^ ((b >> 4) & 0x70); }

// acquire-spin until *c >= tgt (thread 0 only)
__device__ __forceinline__ void spin_acq(unsigned* c, unsigned tgt) {
    unsigned v;
    do {
        asm volatile("ld.acquire.gpu.global.u32 %0, [%1];"
                     : "=r"(v) : "l"(c) : "memory");
    } while (v < tgt);
}
__device__ __forceinline__ void red_rel(unsigned* c) {
    asm volatile("red.release.gpu.global.add.u32 [%0], 1;" :: "l"(c) : "memory");
}

// ---------------- templated block body ----------------
template<int GR, int KT, int LAYER>
__device__ __forceinline__ void run_block(char* dsm, int b0, int n0,
                                          float* __restrict__ out) {
    constexpr int NCH = KT / 128;
    constexpr int WST = KT + 8;
    constexpr int NGF = GR / 32;
    constexpr int NGG = NGF / 2;

    const uint32_t sb0 = (uint32_t)__cvta_generic_to_shared(dsm);
    const uint32_t wb  = sb0 + WOFF;
    const uint32_t mbar = sb0 + MBOFF;

    const int t = threadIdx.x;
    const int w = t >> 5, l = t & 31;
    const int wm = w & 3, wn = w >> 2;
    const int m0 = wm * 32;
    const int n0w = wn * (NGF * 8);
    const int arow = l & 15;
    const int acolb = (l >> 4) * 16;      // bytes
    const int q = l & 3, par = l & 1;
    const int hb = (b0 >> 7) & 1;
    const int grp = n0 >> 9;              // this block's publish group

    if (t == 0) { mbar_init(mbar, 1); mbar_init(mbar + 8, 1); }

    // ---- one-time: weight tile into persistent smem ----
    {
        const __half* Wg = (LAYER == 0) ? (g_w1p + n0 * KT) : (g_w2p + n0 * KT);
#pragma unroll
        for (int i = 0; i < 16; i++) {
            int e = t + 512 * i;
            int r, sg;
            if (KT == 512) { r = e >> 6; sg = e & 63; }
            else           { r = e >> 7; sg = e & 127; }
            cp_cg(wb + (uint32_t)((r * WST + sg * 8) * 2), Wg + r * KT + sg * 8);
        }
        cp_commit(); cp_wait<0>();
        __syncthreads();
    }

    float cc[2][NGG][2];
#pragma unroll
    for (int a = 0; a < 2; a++)
#pragma unroll
        for (int b = 0; b < NGG; b++) { cc[a][b][0] = 0.f; cc[a][b][1] = 0.f; }

    int hidg[NGG];
#pragma unroll
    for (int gg = 0; gg < NGG; gg++) {
        int hidw = 4 * gg + (par ? (2 + (q >> 1)) : (q >> 1));
        hidg[gg] = (n0 >> 2) + wn * (NGF * 2) + hidw;
    }

    unsigned phs0 = 0, phs1 = 0;
    const int K0 = LAYER ? 1 : 0;
    const int K1 = LAYER ? TT : TT - 1;

    for (int k = K0; k <= K1; k++) {
        const int rs = (k + 2) % 3;       // read slot  (= h[k-1]; k=0 -> zeros)
        const int ws = k % 3;             // write slot (= h[k])
        const char* Ag = (const char*)&g_hc3[rs][hb][0][0];

        // chunk-dependency spin (thread 0), then issue TMA
        auto dep_ld = [&](int stage, int ch) {
            if (LAYER == 0) {
                spin_acq(&g_pc1[hb][ch], (unsigned)(4 * k));
            } else {
                if (ch < 4) spin_acq(&g_pc1[hb][ch], (unsigned)(4 * k));
                else        spin_acq(&g_pc2[hb][ch - 4], (unsigned)(8 * (k - 1)));
            }
            bulk_ld(sb0 + (uint32_t)(stage * TILEB), Ag + ch * TILEB,
                    mbar + stage * 8);
        };

        if (t == 0) {
            if (LAYER == 0 && k >= 3)     // ring backpressure: L2 done iter k-2
                spin_acq(&g_pcl2[hb], (unsigned)(32 * (k - 2)));
            dep_ld(0, 0);
            dep_ld(1, 1);
        }

        float acc[2][NGF][4];
#pragma unroll
        for (int a = 0; a < 2; a++)
#pragma unroll
            for (int b = 0; b < NGF; b++)
#pragma unroll
                for (int c = 0; c < 4; c++) acc[a][b][c] = 0.f;

#pragma unroll 1
        for (int ch = 0; ch < NCH; ch++) {
            if (ch & 1) { mbar_wait(mbar + 8, phs1); phs1 ^= 1; }
            else        { mbar_wait(mbar, phs0); phs0 ^= 1; }

            const uint32_t stg = sb0 + (uint32_t)((ch & 1) * TILEB);
#pragma unroll
            for (int ks = 0; ks < 8; ks++) {
                uint32_t ra0 = (uint32_t)((m0 + arow) * 256 + ks * 32 + acolb);
                uint32_t ra1 = ra0 + 16 * 256;
                uint32_t a0, a1, a2, a3, a4, a5, a6, a7;
                ldsm4(a0, a1, a2, a3, stg + swz(ra0));
                ldsm4(a4, a5, a6, a7, stg + swz(ra1));
                const int kcol = ch * 128 + ks * 16 + acolb / 2;
#pragma unroll
                for (int bg = 0; bg < NGF / 2; bg++) {
                    uint32_t b0r, b1r, b2r, b3r;
                    ldsm4(b0r, b1r, b2r, b3r,
                          wb + (uint32_t)(((n0w + bg * 16 + arow) * WST + kcol) * 2));
                    mma16816(acc[0][bg * 2 + 0], a0, a1, a2, a3, b0r, b2r);
                    mma16816(acc[0][bg * 2 + 1], a0, a1, a2, a3, b1r, b3r);
                    mma16816(acc[1][bg * 2 + 0], a4, a5, a6, a7, b0r, b2r);
                    mma16816(acc[1][bg * 2 + 1], a4, a5, a6, a7, b1r, b3r);
                }
            }
            __syncthreads();             // all reads of this stage done
            if (ch + 2 < NCH && t == 0) dep_ld(ch & 1, ch + 2);
        }

        // ---- shuffle epilogue + in-register cell + swizzled tile-major h store ----
        char* hcw = (char*)&g_hc3[ws][hb][0][0];
        const int hoff = (LAYER == 0) ? 0 : 512;
#pragma unroll
        for (int mf = 0; mf < 2; mf++) {
#pragma unroll
            for (int gg = 0; gg < NGG; gg++) {
                float4 bs = ((const float4*)((LAYER == 0) ? g_bs1p : g_bs2p))[hidg[gg]];
                float4 wv;
                if (LAYER == 0) wv = ((const float4*)g_wih1p)[hidg[gg]];
#pragma unroll
                for (int rp = 0; rp < 2; rp++) {
                    float sa0 = acc[mf][2 * gg][rp * 2];
                    float sa1 = acc[mf][2 * gg][rp * 2 + 1];
                    float sb0f = acc[mf][2 * gg + 1][rp * 2];
                    float sb1f = acc[mf][2 * gg + 1][rp * 2 + 1];
                    float oa0 = __shfl_xor_sync(0xFFFFFFFFu, sa0, 1);
                    float oa1 = __shfl_xor_sync(0xFFFFFFFFu, sa1, 1);
                    float ob0 = __shfl_xor_sync(0xFFFFFFFFu, sb0f, 1);
                    float ob1 = __shfl_xor_sync(0xFFFFFFFFu, sb1f, 1);
                    float pi, pf, pg, po;
                    if (par == 0) { pi = sa0; pf = sa1; pg = oa0; po = oa1; }
                    else          { pi = ob0; pf = ob1; pg = sb0f; po = sb1f; }
                    pi += bs.x; pf += bs.y; pg += bs.z; po += bs.w;
                    int growM = b0 + m0 + mf * 16 + rp * 8 + (l >> 2);
                    if (LAYER == 0) {
                        float xv = g_xt[k * BATCH + growM];
                        pi += xv * wv.x; pf += xv * wv.y;
                        pg += xv * wv.z; po += xv * wv.w;
                    }
                    float i_ = sigf(pi), f_ = sigf(pf);
                    float g_ = tanhf_(pg), o_ = sigf(po);
                    float c = fmaf(f_, cc[mf][gg][rp], i_ * g_);
                    cc[mf][gg][rp] = c;
                    float hv = o_ * tanhf_(c);
                    float hv_o = __shfl_xor_sync(0xFFFFFFFFu, hv, 2);
                    if ((l & 2) == 0) {
                        int col = hoff + hidg[gg];
                        uint32_t tb = (uint32_t)((growM & 127) * 256 + (col & 127) * 2);
                        tb = swz(tb);
                        __half2 hp = __floats2half2_rn(hv, hv_o);
                        *(__half2*)(hcw + (col >> 7) * TILEB + tb) = hp;
                    }
                    if (LAYER == 1 && k == TT)
                        out[growM * 512 + hidg[gg]] = hv;
                }
            }
        }

        // ---- publish this step ----
        __syncthreads();
        if (t == 0) {
            if (LAYER == 0) {
                red_rel(&g_pc1[hb][grp]);
            } else {
                red_rel(&g_pc2[hb][grp]);
                red_rel(&g_pcl2[hb]);
            }
        }
    }
}

__global__ __launch_bounds__(NT, 1)
void lstm_persist(float* __restrict__ out) {
    extern __shared__ __align__(16) char dsm[];
    const int bid = blockIdx.x;
    if (bid < 32) {                       // layer 1: 128b x 128g, K=512
        int b0 = (bid & 1) * 128, n0 = (bid >> 1) * 128;
        run_block<128, 512, 0>(dsm, b0, n0, out);
    } else {                              // layer 2: 128b x 64g, K=1024
        int id = bid - 32;
        int b0 = (id & 1) * 128, n0 = (id >> 1) * 64;
        run_block<64, 1024, 1>(dsm, b0, n0, out);
    }
}

extern "C" void kernel_launch(void* const* d_in, const int* in_sizes, int n_in,
                              void* d_out, int out_size) {
    (void)in_sizes; (void)n_in; (void)out_size;
    const float* x    = (const float*)d_in[0];
    const float* Wih1 = (const float*)d_in[1];
    const float* Whh1 = (const float*)d_in[2];
    const float* bih1 = (const float*)d_in[3];
    const float* bhh1 = (const float*)d_in[4];
    const float* Wih2 = (const float*)d_in[5];
    const float* Whh2 = (const float*)d_in[6];
    const float* bih2 = (const float*)d_in[7];
    const float* bhh2 = (const float*)d_in[8];
    float* out = (float*)d_out;

    cudaFuncSetAttribute(lstm_persist, cudaFuncAttributeMaxDynamicSharedMemorySize, DSMEM);

    init_kernel<<<4096, 512>>>(x, Wih1, Whh1, bih1, bhh1, Wih2, Whh2, bih2, bhh2);
    lstm_persist<<<NBL, NT, DSMEM>>>(out);
}